// round 1
// baseline (speedup 1.0000x reference)
#include <cuda_runtime.h>
#include <math.h>

// Problem constants
#define BB   32
#define LL   2048
#define DIN  64
#define NC   32
#define DC   16
#define OUTD 512           // NC*DC
#define EPSQ 1e-7f

#define K1_CHUNKS 16
#define K3_CHUNKS 32       // blocks per batch in routing pass (64 l's each)
#define K3_WARPS  4
#define K3_LPW    16       // l's per warp

// Scratch (static device allocations only — no cudaMalloc allowed)
__device__ float g_colsum_part[BB][K1_CHUNKS][DIN];
__device__ float g_s_part[BB][K3_CHUNKS][NC][DIN];   // 8 MB
__device__ float g_v[BB][NC][DIN];

// ---------------------------------------------------------------------------
// K1: column sums  colsum_part[b][chunk][i] = sum over 128 l's of u[b,l,i]
// grid (K1_CHUNKS, BB), 256 threads
// ---------------------------------------------------------------------------
__global__ void k1_colsum(const float* __restrict__ u) {
    const int b = blockIdx.y, chunk = blockIdx.x;
    const int tid = threadIdx.x;
    const int col4 = tid & 15;   // which float4 column (16 x float4 = 64 floats)
    const int g    = tid >> 4;   // row group 0..15

    const float4* up = (const float4*)(u + ((size_t)b * LL + (size_t)chunk * 128) * DIN);
    float4 acc = make_float4(0.f, 0.f, 0.f, 0.f);
    #pragma unroll
    for (int r = 0; r < 8; r++) {
        float4 x = up[(size_t)(g + r * 16) * 16 + col4];
        acc.x += x.x; acc.y += x.y; acc.z += x.z; acc.w += x.w;
    }
    __shared__ float4 red[16][16];
    red[g][col4] = acc;
    __syncthreads();
    if (tid < 16) {
        float4 s = red[0][tid];
        #pragma unroll
        for (int i = 1; i < 16; i++) {
            float4 x = red[i][tid];
            s.x += x.x; s.y += x.y; s.z += x.z; s.w += x.w;
        }
        ((float4*)g_colsum_part[b][chunk])[tid] = s;
    }
}

// ---------------------------------------------------------------------------
// K2: epilogue — build s (from colsum or partials), compute
//     outputs[n][d] = squash_d( sum_i s[n][i] * W[i][n*16+d] )
//     and v[n][i] = sum_d W[i][n*16+d]*outputs[n][d]   (modes 0,1)
//     or write outputs to d_out (mode 2)
// grid (BB), 512 threads. mode: 0 = iter0 (colsum), 1 = mid iter, 2 = final
// ---------------------------------------------------------------------------
__global__ void k2_update(const float* __restrict__ W, float* __restrict__ out_final,
                          int mode) {
    const int b = blockIdx.x;
    const int tid = threadIdx.x;            // 0..511 ; o = tid = n*16+d
    __shared__ float s_sm[NC][DIN];
    __shared__ float out_sm[NC][DC];

    if (mode == 0) {
        if (tid < DIN) {
            float a = 0.f;
            #pragma unroll
            for (int c = 0; c < K1_CHUNKS; c++) a += g_colsum_part[b][c][tid];
            a *= (1.0f / 32.0f);             // exact uniform c = 1/32
            #pragma unroll
            for (int n = 0; n < NC; n++) s_sm[n][tid] = a;
        }
    } else {
        for (int e = tid; e < NC * DIN; e += 512) {
            float a = 0.f;
            const float* base = (const float*)g_s_part[b];
            #pragma unroll 8
            for (int c = 0; c < K3_CHUNKS; c++) a += base[(size_t)c * NC * DIN + e];
            ((float*)s_sm)[e] = a;
        }
    }
    __syncthreads();

    const int n = tid >> 4;
    const int d = tid & 15;
    float raw = 0.f;
    #pragma unroll
    for (int i = 0; i < DIN; i++)
        raw = fmaf(s_sm[n][i], W[(size_t)i * OUTD + tid], raw);

    // squash: L2 normalize over the 16 d's (contiguous lanes)
    float s2 = raw * raw;
    #pragma unroll
    for (int off = 8; off; off >>= 1)
        s2 += __shfl_xor_sync(0xffffffffu, s2, off, 16);
    float o = raw * rsqrtf(s2 + EPSQ);

    if (mode == 2) {
        out_final[(size_t)b * OUTD + tid] = o;   // [B][NC][DC] row-major
    } else {
        out_sm[n][d] = o;
        __syncthreads();
        for (int e = tid; e < NC * DIN; e += 512) {
            int nn = e >> 6, ii = e & 63;
            float v = 0.f;
            #pragma unroll
            for (int dd = 0; dd < DC; dd++)
                v = fmaf(W[(size_t)ii * OUTD + nn * DC + dd], out_sm[nn][dd], v);
            g_v[b][nn][ii] = v;
        }
    }
}

// ---------------------------------------------------------------------------
// K3: fused routing pass.
// Per (b,l): logits[n] = u[l,:]·v[n,:]; c = softmax over n; s[n,:] += c*u[l,:]
// Warp = one chunk of 16 l's; lane n owns v[n] and s[n] in registers.
// grid (K3_CHUNKS, BB), 128 threads (4 warps).
// ---------------------------------------------------------------------------
__global__ void __launch_bounds__(128, 1) k3_route(const float* __restrict__ u) {
    const int b = blockIdx.y, chunk = blockIdx.x;
    const int w = threadIdx.x >> 5;
    const int lane = threadIdx.x & 31;       // lane == capsule index n

    __shared__ float u_buf[K3_WARPS][64];
    __shared__ float s_blk[K3_WARPS][NC][65];   // padded: conflict-free stores

    // Load v[b][lane][:] into registers (once)
    float4 v4[16];
    const float4* vp = (const float4*)(&g_v[b][lane][0]);
    #pragma unroll
    for (int k = 0; k < 16; k++) v4[k] = vp[k];

    float4 s4[16];
    #pragma unroll
    for (int k = 0; k < 16; k++) s4[k] = make_float4(0.f, 0.f, 0.f, 0.f);

    const int l0 = chunk * (K3_WARPS * K3_LPW) + w * K3_LPW;
    const float* ub = u + ((size_t)b * LL + l0) * DIN;

    for (int j = 0; j < K3_LPW; j++) {
        // cooperative row load: 64 floats via one float2 per lane
        float2 uu = ((const float2*)(ub + (size_t)j * DIN))[lane];
        __syncwarp();                         // WAR vs previous iteration's reads
        ((float2*)u_buf[w])[lane] = uu;
        __syncwarp();
        const float4* ub4 = (const float4*)u_buf[w];

        // logits: lane n dots u with its v row
        float logit = 0.f;
        #pragma unroll
        for (int k = 0; k < 16; k++) {
            float4 x = ub4[k];
            logit = fmaf(x.x, v4[k].x, logit);
            logit = fmaf(x.y, v4[k].y, logit);
            logit = fmaf(x.z, v4[k].z, logit);
            logit = fmaf(x.w, v4[k].w, logit);
        }
        // softmax across the 32 lanes (= 32 capsules)
        float m = logit;
        #pragma unroll
        for (int off = 16; off; off >>= 1)
            m = fmaxf(m, __shfl_xor_sync(0xffffffffu, m, off));
        float e = expf(logit - m);
        float ssum = e;
        #pragma unroll
        for (int off = 16; off; off >>= 1)
            ssum += __shfl_xor_sync(0xffffffffu, ssum, off);
        float c = __fdividef(e, ssum);

        // accumulate s[n,:] += c * u[l,:]
        #pragma unroll
        for (int k = 0; k < 16; k++) {
            float4 x = ub4[k];
            s4[k].x = fmaf(c, x.x, s4[k].x);
            s4[k].y = fmaf(c, x.y, s4[k].y);
            s4[k].z = fmaf(c, x.z, s4[k].z);
            s4[k].w = fmaf(c, x.w, s4[k].w);
        }
    }

    // dump register s into padded smem (stride 65 -> banks (n+i)%32, conflict-free)
    #pragma unroll
    for (int k = 0; k < 16; k++) {
        s_blk[w][lane][4 * k + 0] = s4[k].x;
        s_blk[w][lane][4 * k + 1] = s4[k].y;
        s_blk[w][lane][4 * k + 2] = s4[k].z;
        s_blk[w][lane][4 * k + 3] = s4[k].w;
    }
    __syncthreads();

    // cross-warp reduce, deterministic, coalesced write of this block's partial
    float* outp = (float*)g_s_part[b][chunk];
    for (int e = threadIdx.x; e < NC * DIN; e += 128) {
        int n = e >> 6, i = e & 63;
        outp[e] = s_blk[0][n][i] + s_blk[1][n][i] + s_blk[2][n][i] + s_blk[3][n][i];
    }
}

// ---------------------------------------------------------------------------
extern "C" void kernel_launch(void* const* d_in, const int* in_sizes, int n_in,
                              void* d_out, int out_size) {
    const float* u = (const float*)d_in[0];   // [32, 2048, 64]
    const float* W = (const float*)d_in[1];   // [1, 64, 512]
    float* out = (float*)d_out;               // [32, 32, 16]

    // iteration 0: uniform c -> colsum path
    k1_colsum<<<dim3(K1_CHUNKS, BB), 256>>>(u);
    k2_update<<<BB, 512>>>(W, out, 0);        // outputs0 + v0
    // iteration 1
    k3_route<<<dim3(K3_CHUNKS, BB), 128>>>(u);
    k2_update<<<BB, 512>>>(W, out, 1);        // outputs1 + v1
    // iteration 2 (final)
    k3_route<<<dim3(K3_CHUNKS, BB), 128>>>(u);
    k2_update<<<BB, 512>>>(W, out, 2);        // outputs2 -> d_out
}

// round 3
// speedup vs baseline: 1.6040x; 1.6040x over previous
#include <cuda_runtime.h>
#include <math.h>

// Problem constants
#define BB   32
#define LL   2048
#define DIN  64
#define NC   32
#define DC   16
#define OUTD 512           // NC*DC
#define EPSQ 1e-7f

#define K1_CHUNKS 16
#define K3_CHUNKS 32       // blocks per batch in routing pass (64 l's each)
#define K3_WARPS  4
#define K3_LPW    16       // l's per warp

// Scratch (static device allocations only — no cudaMalloc allowed)
__device__ float g_colsum_part[BB][K1_CHUNKS][DIN];
__device__ float g_s_part[BB][K3_CHUNKS][NC][DIN];   // 8 MB
__device__ float g_v[BB][NC][DIN];

// ---------------------------------------------------------------------------
// K1: column sums  colsum_part[b][chunk][i] = sum over 128 l's of u[b,l,i]
// grid (K1_CHUNKS, BB), 256 threads
// ---------------------------------------------------------------------------
__global__ void k1_colsum(const float* __restrict__ u) {
    const int b = blockIdx.y, chunk = blockIdx.x;
    const int tid = threadIdx.x;
    const int col4 = tid & 15;   // which float4 column (16 x float4 = 64 floats)
    const int g    = tid >> 4;   // row group 0..15

    const float4* up = (const float4*)(u + ((size_t)b * LL + (size_t)chunk * 128) * DIN);
    float4 acc = make_float4(0.f, 0.f, 0.f, 0.f);
    #pragma unroll
    for (int r = 0; r < 8; r++) {
        float4 x = up[(size_t)(g + r * 16) * 16 + col4];
        acc.x += x.x; acc.y += x.y; acc.z += x.z; acc.w += x.w;
    }
    __shared__ float4 red[16][16];
    red[g][col4] = acc;
    __syncthreads();
    if (tid < 16) {
        float4 s = red[0][tid];
        #pragma unroll
        for (int i = 1; i < 16; i++) {
            float4 x = red[i][tid];
            s.x += x.x; s.y += x.y; s.z += x.z; s.w += x.w;
        }
        ((float4*)g_colsum_part[b][chunk])[tid] = s;
    }
}

// ---------------------------------------------------------------------------
// K2: per-(b,n) epilogue. grid (NC, BB), 32 threads (1 warp).
//   s[n][i]   = reduce partials (mode 0: colsum/32 uniform; else: g_s_part)
//   raw[d]    = sum_i s[i] * W[i][n*16+d]
//   out[n][d] = raw[d] / sqrt(sum_d raw^2 + eps)
//   mode 0/1: also v[n][i] = sum_d W[i][n*16+d]*out[d]  -> g_v
//   mode 2:   write out to d_out
// 1024 independent warps -> latency of the strided partial reads fully hidden.
// ---------------------------------------------------------------------------
__global__ void __launch_bounds__(32, 16) k2_update(const float* __restrict__ W,
                                                    float* __restrict__ out_final,
                                                    int mode) {
    const int n = blockIdx.x, b = blockIdx.y;
    const int lane = threadIdx.x;
    __shared__ float s_sm[DIN];
    __shared__ float out_sm[DC];

    float a0 = 0.f, a1 = 0.f;
    if (mode == 0) {
        #pragma unroll
        for (int c = 0; c < K1_CHUNKS; c++) {
            a0 += g_colsum_part[b][c][lane];
            a1 += g_colsum_part[b][c][lane + 32];
        }
        a0 *= (1.0f / 32.0f);
        a1 *= (1.0f / 32.0f);
    } else {
        #pragma unroll
        for (int c = 0; c < K3_CHUNKS; c++) {
            const float* base = &g_s_part[b][c][n][0];
            a0 += base[lane];
            a1 += base[lane + 32];
        }
    }
    s_sm[lane]      = a0;
    s_sm[lane + 32] = a1;
    __syncwarp();

    // raw[d] for d = lane (<16)
    float raw = 0.f;
    if (lane < DC) {
        const float* Wc = W + (size_t)n * DC + lane;   // W[i*512 + n*16 + lane]
        #pragma unroll
        for (int i = 0; i < DIN; i++)
            raw = fmaf(s_sm[i], Wc[(size_t)i * OUTD], raw);
    }
    float s2 = raw * raw;
    #pragma unroll
    for (int off = 8; off; off >>= 1)
        s2 += __shfl_xor_sync(0xffffffffu, s2, off, 16);
    float o = raw * rsqrtf(s2 + EPSQ);

    if (mode == 2) {
        if (lane < DC) out_final[(size_t)b * OUTD + (size_t)n * DC + lane] = o;
    } else {
        if (lane < DC) out_sm[lane] = o;
        __syncwarp();
        // v[n][i] for i = lane, lane+32
        const float* Wr0 = W + (size_t)lane * OUTD + (size_t)n * DC;
        const float* Wr1 = W + (size_t)(lane + 32) * OUTD + (size_t)n * DC;
        float v0 = 0.f, v1 = 0.f;
        #pragma unroll
        for (int d = 0; d < DC; d++) {
            float od = out_sm[d];
            v0 = fmaf(Wr0[d], od, v0);
            v1 = fmaf(Wr1[d], od, v1);
        }
        g_v[b][n][lane]      = v0;
        g_v[b][n][lane + 32] = v1;
    }
}

// ---------------------------------------------------------------------------
// K3: fused routing pass, 2 l's per iteration for ILP.
// Per (b,l): logits[n] = u[l,:]·v[n,:]; c = softmax over n; s[n,:] += c*u[l,:]
// Warp = 16 l's; lane n owns v[n] and s[n] in registers.
// No max-subtract in softmax: |logit| <= |u_row||v| << 88, exp is safe.
// grid (K3_CHUNKS, BB), 128 threads (4 warps).
// ---------------------------------------------------------------------------
__global__ void __launch_bounds__(128, 1) k3_route(const float* __restrict__ u) {
    const int b = blockIdx.y, chunk = blockIdx.x;
    const int w = threadIdx.x >> 5;
    const int lane = threadIdx.x & 31;       // lane == capsule index n

    __shared__ float u_buf[K3_WARPS][2][64];
    __shared__ float s_blk[K3_WARPS][NC][65];   // padded: conflict-free stores

    // Load v[b][lane][:] into registers (once)
    float4 v4[16];
    const float4* vp = (const float4*)(&g_v[b][lane][0]);
    #pragma unroll
    for (int k = 0; k < 16; k++) v4[k] = vp[k];

    float4 s4[16];
    #pragma unroll
    for (int k = 0; k < 16; k++) s4[k] = make_float4(0.f, 0.f, 0.f, 0.f);

    const int l0 = chunk * (K3_WARPS * K3_LPW) + w * K3_LPW;
    const float* ub = u + ((size_t)b * LL + l0) * DIN;

    for (int j = 0; j < K3_LPW; j += 2) {
        // cooperative row loads: 2 rows of 64 floats, one float2 per lane each
        float2 ra = ((const float2*)(ub + (size_t)j * DIN))[lane];
        float2 rb = ((const float2*)(ub + (size_t)(j + 1) * DIN))[lane];
        __syncwarp();                         // WAR vs previous iteration's reads
        ((float2*)u_buf[w][0])[lane] = ra;
        ((float2*)u_buf[w][1])[lane] = rb;
        __syncwarp();
        const float4* uA = (const float4*)u_buf[w][0];
        const float4* uB = (const float4*)u_buf[w][1];

        // two independent logit dot-products, 2 accumulators each
        float lA0 = 0.f, lA1 = 0.f, lB0 = 0.f, lB1 = 0.f;
        #pragma unroll
        for (int k = 0; k < 16; k += 2) {
            float4 xA = uA[k], yA = uA[k + 1];
            float4 xB = uB[k], yB = uB[k + 1];
            lA0 = fmaf(xA.x, v4[k].x, lA0);     lA0 = fmaf(xA.y, v4[k].y, lA0);
            lA0 = fmaf(xA.z, v4[k].z, lA0);     lA0 = fmaf(xA.w, v4[k].w, lA0);
            lA1 = fmaf(yA.x, v4[k + 1].x, lA1); lA1 = fmaf(yA.y, v4[k + 1].y, lA1);
            lA1 = fmaf(yA.z, v4[k + 1].z, lA1); lA1 = fmaf(yA.w, v4[k + 1].w, lA1);
            lB0 = fmaf(xB.x, v4[k].x, lB0);     lB0 = fmaf(xB.y, v4[k].y, lB0);
            lB0 = fmaf(xB.z, v4[k].z, lB0);     lB0 = fmaf(xB.w, v4[k].w, lB0);
            lB1 = fmaf(yB.x, v4[k + 1].x, lB1); lB1 = fmaf(yB.y, v4[k + 1].y, lB1);
            lB1 = fmaf(yB.z, v4[k + 1].z, lB1); lB1 = fmaf(yB.w, v4[k + 1].w, lB1);
        }
        float eA = __expf(lA0 + lA1);
        float eB = __expf(lB0 + lB1);
        float sA = eA, sB = eB;
        #pragma unroll
        for (int off = 16; off; off >>= 1) {
            sA += __shfl_xor_sync(0xffffffffu, sA, off);
            sB += __shfl_xor_sync(0xffffffffu, sB, off);
        }
        float cA = __fdividef(eA, sA);
        float cB = __fdividef(eB, sB);

        // accumulate s[n,:] += cA*uA + cB*uB
        #pragma unroll
        for (int k = 0; k < 16; k++) {
            float4 xA = uA[k], xB = uB[k];
            s4[k].x = fmaf(cA, xA.x, fmaf(cB, xB.x, s4[k].x));
            s4[k].y = fmaf(cA, xA.y, fmaf(cB, xB.y, s4[k].y));
            s4[k].z = fmaf(cA, xA.z, fmaf(cB, xB.z, s4[k].z));
            s4[k].w = fmaf(cA, xA.w, fmaf(cB, xB.w, s4[k].w));
        }
    }

    // dump register s into padded smem (stride 65 -> conflict-free)
    #pragma unroll
    for (int k = 0; k < 16; k++) {
        s_blk[w][lane][4 * k + 0] = s4[k].x;
        s_blk[w][lane][4 * k + 1] = s4[k].y;
        s_blk[w][lane][4 * k + 2] = s4[k].z;
        s_blk[w][lane][4 * k + 3] = s4[k].w;
    }
    __syncthreads();

    // cross-warp reduce, deterministic, coalesced write of this block's partial
    float* outp = (float*)g_s_part[b][chunk];
    for (int e = threadIdx.x; e < NC * DIN; e += 128) {
        int n = e >> 6, i = e & 63;
        outp[e] = s_blk[0][n][i] + s_blk[1][n][i] + s_blk[2][n][i] + s_blk[3][n][i];
    }
}

// ---------------------------------------------------------------------------
extern "C" void kernel_launch(void* const* d_in, const int* in_sizes, int n_in,
                              void* d_out, int out_size) {
    const float* u = (const float*)d_in[0];   // [32, 2048, 64]
    const float* W = (const float*)d_in[1];   // [1, 64, 512]
    float* out = (float*)d_out;               // [32, 32, 16]

    // iteration 0: uniform c -> colsum path
    k1_colsum<<<dim3(K1_CHUNKS, BB), 256>>>(u);
    k2_update<<<dim3(NC, BB), 32>>>(W, out, 0);   // outputs0 + v0
    // iteration 1
    k3_route<<<dim3(K3_CHUNKS, BB), 128>>>(u);
    k2_update<<<dim3(NC, BB), 32>>>(W, out, 1);   // outputs1 + v1
    // iteration 2 (final)
    k3_route<<<dim3(K3_CHUNKS, BB), 128>>>(u);
    k2_update<<<dim3(NC, BB), 32>>>(W, out, 2);   // outputs2 -> d_out
}